// round 2
// baseline (speedup 1.0000x reference)
#include <cuda_runtime.h>
#include <cuda_bf16.h>
#include <cstdint>

// SSL2d: per-channel sub-pixel bilinear shift with zero padding.
// x: [B=32, C=384, H=56, W=56] fp32, a,b: [C] fp32.
// out[n,c,h,w] = bilinear sample of x[n,c] at (h + a[c], w + b[c]), zero-pad OOB.
//
// R2 strategy: stage each plane through a zero-padded SMEM tile.
//  - global read = 1 coalesced float4/thread (exactly the plane)
//  - padded tile (rows -1..56, cols -1..56 covered) => branch-free LDS reads
//  - row stride 68 floats (=4 mod 32 banks) => no inter-row bank conflicts

#define SSL_H 56
#define SSL_W 56
#define SSL_C 384
#define VEC_PER_ROW (SSL_W / 4)             // 14
#define VEC_PER_PLANE (SSL_H * VEC_PER_ROW) // 784 threads = 1 float4 each

#define TILE_STRIDE 68                      // floats per smem row (mult of 4, !=0 mod trouble)
#define TILE_ROWS 58                        // rows -1..56 (data at +1)
#define TILE_FLOATS (TILE_ROWS * TILE_STRIDE)   // 3944
#define DATA_COL_OFF 4                      // data col 0 at smem col 4 (16B aligned)

__global__ __launch_bounds__(VEC_PER_PLANE, 2)
void ssl2d_kernel(const float* __restrict__ x,
                  const float* __restrict__ a,
                  const float* __restrict__ b,
                  float* __restrict__ out) {
    __shared__ float tile[TILE_FLOATS];

    const int plane = blockIdx.x;           // n * C + c
    const int c = plane - (plane / SSL_C) * SSL_C;

    const float av = __ldg(a + c);
    const float bv = __ldg(b + c);
    const float iaf = floorf(av);
    const float ibf = floorf(bv);
    const float fa = av - iaf;
    const float fb = bv - ibf;
    const int ia = (int)iaf;
    const int ib = (int)ibf;

    const float w00 = (1.0f - fa) * (1.0f - fb);
    const float w01 = (1.0f - fa) * fb;
    const float w10 = fa * (1.0f - fb);
    const float w11 = fa * fb;

    const float* __restrict__ xp = x + (size_t)plane * (SSL_H * SSL_W);
    float* __restrict__ op       = out + (size_t)plane * (SSL_H * SSL_W);

    const int vid = threadIdx.x;            // 0..783
    const int h = vid / VEC_PER_ROW;
    const int w = (vid - h * VEC_PER_ROW) * 4;

    if (ia >= -1 && ia <= 0 && ib >= -1 && ib <= 0) {
        // ---- fast path: padded smem tile, branch-free reads ----
        // zero-fill whole tile (986 float4, <=2 per thread)
        float4 z4 = make_float4(0.f, 0.f, 0.f, 0.f);
        #pragma unroll
        for (int i = vid; i < TILE_FLOATS / 4; i += VEC_PER_PLANE)
            reinterpret_cast<float4*>(tile)[i] = z4;
        __syncthreads();

        // coalesced plane load -> padded interior
        float4 v = reinterpret_cast<const float4*>(xp)[vid];
        *reinterpret_cast<float4*>(&tile[(h + 1) * TILE_STRIDE + DATA_COL_OFF + w]) = v;
        __syncthreads();

        const int h0 = h + ia;                  // in [-1, 55]
        const int wbase = w + ib;               // in [-1, 52]
        const float* p0 = &tile[(h0 + 1) * TILE_STRIDE + DATA_COL_OFF + wbase];
        const float* p1 = p0 + TILE_STRIDE;

        float r0[5], r1[5];
        #pragma unroll
        for (int i = 0; i < 5; i++) { r0[i] = p0[i]; r1[i] = p1[i]; }

        float4 o;
        o.x = w00 * r0[0] + w01 * r0[1] + w10 * r1[0] + w11 * r1[1];
        o.y = w00 * r0[1] + w01 * r0[2] + w10 * r1[1] + w11 * r1[2];
        o.z = w00 * r0[2] + w01 * r0[3] + w10 * r1[2] + w11 * r1[3];
        o.w = w00 * r0[3] + w01 * r0[4] + w10 * r1[3] + w11 * r1[4];

        *reinterpret_cast<float4*>(op + h * SSL_W + w) = o;
    } else {
        // ---- generic fallback (never taken for |a|,|b| <= 1): predicated LDG ----
        const int h0 = h + ia;
        const int h1 = h0 + 1;
        const bool vh0 = (h0 >= 0) & (h0 < SSL_H);
        const bool vh1 = (h1 >= 0) & (h1 < SSL_H);
        const int wbase = w + ib;
        const float* row0 = xp + h0 * SSL_W;
        const float* row1 = xp + h1 * SSL_W;

        float r0[5], r1[5];
        #pragma unroll
        for (int i = 0; i < 5; i++) {
            const int ws = wbase + i;
            const bool vw = (ws >= 0) & (ws < SSL_W);
            r0[i] = (vh0 & vw) ? __ldg(row0 + ws) : 0.0f;
            r1[i] = (vh1 & vw) ? __ldg(row1 + ws) : 0.0f;
        }

        float4 o;
        o.x = w00 * r0[0] + w01 * r0[1] + w10 * r1[0] + w11 * r1[1];
        o.y = w00 * r0[1] + w01 * r0[2] + w10 * r1[1] + w11 * r1[2];
        o.z = w00 * r0[2] + w01 * r0[3] + w10 * r1[2] + w11 * r1[3];
        o.w = w00 * r0[3] + w01 * r0[4] + w10 * r1[3] + w11 * r1[4];

        *reinterpret_cast<float4*>(op + h * SSL_W + w) = o;
    }
}

extern "C" void kernel_launch(void* const* d_in, const int* in_sizes, int n_in,
                              void* d_out, int out_size) {
    const float* x = (const float*)d_in[0];
    const float* a = (const float*)d_in[1];
    const float* b = (const float*)d_in[2];
    float* out = (float*)d_out;

    const int B = 32;
    const int planes = B * SSL_C;           // 12288
    ssl2d_kernel<<<planes, VEC_PER_PLANE>>>(x, a, b, out);
}

// round 3
// speedup vs baseline: 1.5841x; 1.5841x over previous
#include <cuda_runtime.h>
#include <cuda_bf16.h>
#include <cstdint>

// SSL2d: per-channel sub-pixel bilinear shift with zero padding.
// x: [B=32, C=384, H=56, W=56] fp32, a,b: [C] fp32.
//
// R3: vectorized reads + warp shuffle, no smem.
//  - 16 threads/row (14 active), warp = exactly 2 rows -> shuffles stay in-warp
//  - each thread: 2 predicated LDG.128 (source rows h0,h1 at its own aligned col)
//  - the one extra boundary element per row comes from __shfl of the neighbor lane
//  - all row-seam / edge shuffle cases are OOB -> forced to 0 (zero padding)

#define SSL_H 56
#define SSL_W 56
#define SSL_C 384
#define TPR 16                              // threads per row (14 active)
#define NTHREADS (SSL_H * TPR)              // 896

__global__ __launch_bounds__(NTHREADS, 2)
void ssl2d_kernel(const float* __restrict__ x,
                  const float* __restrict__ a,
                  const float* __restrict__ b,
                  float* __restrict__ out) {
    const int plane = blockIdx.x;           // n * C + c
    const int c = plane - (plane / SSL_C) * SSL_C;

    const float av = __ldg(a + c);
    const float bv = __ldg(b + c);
    const float iaf = floorf(av);
    const float ibf = floorf(bv);
    const float fa = av - iaf;
    const float fb = bv - ibf;
    const int ia = (int)iaf;
    const int ib = (int)ibf;

    const float w00 = (1.0f - fa) * (1.0f - fb);
    const float w01 = (1.0f - fa) * fb;
    const float w10 = fa * (1.0f - fb);
    const float w11 = fa * fb;

    const float* __restrict__ xp = x + (size_t)plane * (SSL_H * SSL_W);
    float* __restrict__ op       = out + (size_t)plane * (SSL_H * SSL_W);

    const int tid = threadIdx.x;
    const int h = tid >> 4;                 // 0..55
    const int j = tid & 15;                 // 0..15 (14,15 inactive)
    const int w = j * 4;
    const bool active = (j < 14);

    const int h0 = h + ia;
    const int h1 = h0 + 1;
    const bool vh0 = (h0 >= 0) & (h0 < SSL_H);
    const bool vh1 = (h1 >= 0) & (h1 < SSL_H);

    if (ib >= -1 && ib <= 0) {
        // ---- fast path: 2 aligned LDG.128 + 1 shfl per row ----
        float4 q0 = make_float4(0.f, 0.f, 0.f, 0.f);
        float4 q1 = q0;
        if (active & vh0) q0 = *reinterpret_cast<const float4*>(xp + h0 * SSL_W + w);
        if (active & vh1) q1 = *reinterpret_cast<const float4*>(xp + h1 * SSL_W + w);

        float r0[5], r1[5];
        if (ib == 0) {
            // window cols [w .. w+4]; extra = next lane's .x (w+4), OOB at j==13
            float e0 = __shfl_down_sync(0xffffffffu, q0.x, 1);
            float e1 = __shfl_down_sync(0xffffffffu, q1.x, 1);
            if (w + 4 >= SSL_W) { e0 = 0.f; e1 = 0.f; }
            r0[0]=q0.x; r0[1]=q0.y; r0[2]=q0.z; r0[3]=q0.w; r0[4]=e0;
            r1[0]=q1.x; r1[1]=q1.y; r1[2]=q1.z; r1[3]=q1.w; r1[4]=e1;
        } else {
            // ib == -1: window cols [w-1 .. w+3]; extra = prev lane's .w (w-1), OOB at j==0
            float e0 = __shfl_up_sync(0xffffffffu, q0.w, 1);
            float e1 = __shfl_up_sync(0xffffffffu, q1.w, 1);
            if (j == 0) { e0 = 0.f; e1 = 0.f; }
            r0[0]=e0; r0[1]=q0.x; r0[2]=q0.y; r0[3]=q0.z; r0[4]=q0.w;
            r1[0]=e1; r1[1]=q1.x; r1[2]=q1.y; r1[3]=q1.z; r1[4]=q1.w;
        }

        if (active) {
            float4 o;
            o.x = w00 * r0[0] + w01 * r0[1] + w10 * r1[0] + w11 * r1[1];
            o.y = w00 * r0[1] + w01 * r0[2] + w10 * r1[1] + w11 * r1[2];
            o.z = w00 * r0[2] + w01 * r0[3] + w10 * r1[2] + w11 * r1[3];
            o.w = w00 * r0[3] + w01 * r0[4] + w10 * r1[3] + w11 * r1[4];
            *reinterpret_cast<float4*>(op + h * SSL_W + w) = o;
        }
    } else if (active) {
        // ---- generic fallback (shifts outside [-1,0]): predicated scalar LDG ----
        const int wbase = w + ib;
        const float* row0 = xp + h0 * SSL_W;
        const float* row1 = xp + h1 * SSL_W;

        float r0[5], r1[5];
        #pragma unroll
        for (int i = 0; i < 5; i++) {
            const int ws = wbase + i;
            const bool vw = (ws >= 0) & (ws < SSL_W);
            r0[i] = (vh0 & vw) ? __ldg(row0 + ws) : 0.0f;
            r1[i] = (vh1 & vw) ? __ldg(row1 + ws) : 0.0f;
        }

        float4 o;
        o.x = w00 * r0[0] + w01 * r0[1] + w10 * r1[0] + w11 * r1[1];
        o.y = w00 * r0[1] + w01 * r0[2] + w10 * r1[1] + w11 * r1[2];
        o.z = w00 * r0[2] + w01 * r0[3] + w10 * r1[2] + w11 * r1[3];
        o.w = w00 * r0[3] + w01 * r0[4] + w10 * r1[3] + w11 * r1[4];
        *reinterpret_cast<float4*>(op + h * SSL_W + w) = o;
    }
}

extern "C" void kernel_launch(void* const* d_in, const int* in_sizes, int n_in,
                              void* d_out, int out_size) {
    const float* x = (const float*)d_in[0];
    const float* a = (const float*)d_in[1];
    const float* b = (const float*)d_in[2];
    float* out = (float*)d_out;

    const int B = 32;
    const int planes = B * SSL_C;           // 12288
    ssl2d_kernel<<<planes, NTHREADS>>>(x, a, b, out);
}

// round 6
// speedup vs baseline: 2.1487x; 1.3564x over previous
#include <cuda_runtime.h>
#include <cuda_bf16.h>
#include <cstdint>

// SSL2d: per-channel sub-pixel bilinear shift with zero padding.
// x: [B=32, C=384, H=56, W=56] fp32, a,b: [C] fp32.
//
// R4: 4 output rows per thread (5 source-row LDG.128, MLP=5), warp shuffle for
// the one boundary element per row, factored bilinear blend.
//  - 16 lanes per column-group (14 active), rowgroup = 4 rows; warp = 2 rowgroups
//  - shuffles stay in-warp; all edge/seam shuffle cases are forced-zero anyway

#define SSL_H 56
#define SSL_W 56
#define SSL_C 384
#define NTHREADS 224                        // 14 rowgroups * 16 lanes

__global__ __launch_bounds__(NTHREADS, 7)
void ssl2d_kernel(const float* __restrict__ x,
                  const float* __restrict__ a,
                  const float* __restrict__ b,
                  float* __restrict__ out) {
    const int plane = blockIdx.x;           // n * C + c
    const int c = plane - (plane / SSL_C) * SSL_C;

    const float av = __ldg(a + c);
    const float bv = __ldg(b + c);
    const float iaf = floorf(av);
    const float ibf = floorf(bv);
    const float fa = av - iaf;
    const float fb = bv - ibf;
    const int ia = (int)iaf;
    const int ib = (int)ibf;

    const float* __restrict__ xp = x + (size_t)plane * (SSL_H * SSL_W);
    float* __restrict__ op       = out + (size_t)plane * (SSL_H * SSL_W);

    const int tid = threadIdx.x;
    const int j = tid & 15;                 // lane within rowgroup, 0..15 (14,15 idle)
    const int rg = tid >> 4;                // rowgroup 0..13
    const int hbase = rg << 2;              // first output row of this thread
    const int w = j << 2;
    const bool active = (j < 14);

    if (ia >= -1 && ia <= 0 && ib >= -1 && ib <= 0) {
        // ---- fast path ----
        // load 5 source rows (aligned float4 each), all issued up-front
        float4 q[5];
        #pragma unroll
        for (int k = 0; k < 5; k++) {
            const int s = hbase + ia + k;
            q[k] = make_float4(0.f, 0.f, 0.f, 0.f);
            if (active & (s >= 0) & (s < SSL_H))
                q[k] = *reinterpret_cast<const float4*>(xp + s * SSL_W + w);
        }

        // horizontal blend per source row
        const float fb1 = 1.0f - fb;
        float4 Hk[5];
        if (ib == 0) {
            #pragma unroll
            for (int k = 0; k < 5; k++) {
                float e = __shfl_down_sync(0xffffffffu, q[k].x, 1); // col w+4
                if (j >= 13) e = 0.f;                               // w+4 >= 56
                Hk[k].x = fb1 * q[k].x + fb * q[k].y;
                Hk[k].y = fb1 * q[k].y + fb * q[k].z;
                Hk[k].z = fb1 * q[k].z + fb * q[k].w;
                Hk[k].w = fb1 * q[k].w + fb * e;
            }
        } else {
            #pragma unroll
            for (int k = 0; k < 5; k++) {
                float e = __shfl_up_sync(0xffffffffu, q[k].w, 1);   // col w-1
                if (j == 0) e = 0.f;                                // w-1 < 0
                Hk[k].x = fb1 * e       + fb * q[k].x;
                Hk[k].y = fb1 * q[k].x  + fb * q[k].y;
                Hk[k].z = fb1 * q[k].y  + fb * q[k].z;
                Hk[k].w = fb1 * q[k].z  + fb * q[k].w;
            }
        }

        // vertical blend + store 4 rows
        if (active) {
            const float fa1 = 1.0f - fa;
            #pragma unroll
            for (int r = 0; r < 4; r++) {
                float4 o;
                o.x = fa1 * Hk[r].x + fa * Hk[r + 1].x;
                o.y = fa1 * Hk[r].y + fa * Hk[r + 1].y;
                o.z = fa1 * Hk[r].z + fa * Hk[r + 1].z;
                o.w = fa1 * Hk[r].w + fa * Hk[r + 1].w;
                *reinterpret_cast<float4*>(op + (hbase + r) * SSL_W + w) = o;
            }
        }
    } else if (active) {
        // ---- generic fallback (shifts outside [-1,0]): predicated scalar LDG ----
        const float w00 = (1.0f - fa) * (1.0f - fb);
        const float w01 = (1.0f - fa) * fb;
        const float w10 = fa * (1.0f - fb);
        const float w11 = fa * fb;

        #pragma unroll
        for (int r = 0; r < 4; r++) {
            const int h = hbase + r;
            const int h0 = h + ia;
            const int h1 = h0 + 1;
            const bool vh0 = (h0 >= 0) & (h0 < SSL_H);
            const bool vh1 = (h1 >= 0) & (h1 < SSL_H);
            const int wbase = w + ib;
            const float* row0 = xp + h0 * SSL_W;
            const float* row1 = xp + h1 * SSL_W;

            float r0[5], r1[5];
            #pragma unroll
            for (int i = 0; i < 5; i++) {
                const int ws = wbase + i;
                const bool vw = (ws >= 0) & (ws < SSL_W);
                r0[i] = (vh0 & vw) ? __ldg(row0 + ws) : 0.0f;
                r1[i] = (vh1 & vw) ? __ldg(row1 + ws) : 0.0f;
            }

            float4 o;
            o.x = w00 * r0[0] + w01 * r0[1] + w10 * r1[0] + w11 * r1[1];
            o.y = w00 * r0[1] + w01 * r0[2] + w10 * r1[1] + w11 * r1[2];
            o.z = w00 * r0[2] + w01 * r0[3] + w10 * r1[2] + w11 * r1[3];
            o.w = w00 * r0[3] + w01 * r0[4] + w10 * r1[3] + w11 * r1[4];
            *reinterpret_cast<float4*>(op + h * SSL_W + w) = o;
        }
    }
}

extern "C" void kernel_launch(void* const* d_in, const int* in_sizes, int n_in,
                              void* d_out, int out_size) {
    const float* x = (const float*)d_in[0];
    const float* a = (const float*)d_in[1];
    const float* b = (const float*)d_in[2];
    float* out = (float*)d_out;

    const int B = 32;
    const int planes = B * SSL_C;           // 12288
    ssl2d_kernel<<<planes, NTHREADS>>>(x, a, b, out);
}